// round 16
// baseline (speedup 1.0000x reference)
#include <cuda_runtime.h>
#include <cuda_fp16.h>

#define EPSILON 1e-4f
#define MARG    0.001953125f    // 1/512
#define NBLK    16
#define NCTA    128
#define STH     1024            // 32 warps/CTA: 2x warp supply, same global structure
#define QS      16.0f           // int8 quant scale (step 1/16)
#define QSI     0.0625f         // 1/QS

// Scratch (static device globals — no allocation)
__device__ unsigned gBq[8 * 512 * 8];         // int8-packed b rows: [row][8 u32] = 32 bytes
__device__ float    gPartial[8][16][512];     // col partial sums
__device__ float    gSpart[8][16];            // per-block cost sums
__device__ unsigned gBarCnt[8];               // barrier counters (self-reset per gen)
__device__ unsigned gBarPhase[8];             // phase flags; local phase seeded at entry

// ---- split-phase sense-reversing barrier: 16 arrivals per batch ----
__device__ __forceinline__ bool bar_arrive(int b, int phase) {
    __syncthreads();
    bool last = false;
    if (threadIdx.x == 0) {
        unsigned old;
        asm volatile("atom.acq_rel.gpu.global.add.u32 %0, [%1], %2;"
                     : "=r"(old) : "l"(&gBarCnt[b]), "r"(1u) : "memory");
        if (old == NBLK - 1) {
            unsigned z = 0, np = (unsigned)(phase ^ 1);
            asm volatile("st.relaxed.gpu.global.u32 [%0], %1;" :: "l"(&gBarCnt[b]), "r"(z) : "memory");
            asm volatile("st.release.gpu.global.u32 [%0], %1;" :: "l"(&gBarPhase[b]), "r"(np) : "memory");
            last = true;
        }
    }
    return last;   // meaningful on tid 0 only
}
__device__ __forceinline__ void bar_wait(int b, int& phase, bool last) {
    if (threadIdx.x == 0 && !last) {
        unsigned cur;
        do {
            asm volatile("ld.acquire.gpu.global.u32 %0, [%1];"
                         : "=r"(cur) : "l"(&gBarPhase[b]) : "memory");
        } while (cur == (unsigned)phase);
    }
    phase ^= 1;
    __syncthreads();
}

__device__ __forceinline__ half2 u2h(unsigned u) { return *reinterpret_cast<half2*>(&u); }
__device__ __forceinline__ unsigned h2u(half2 h) { return *reinterpret_cast<unsigned*>(&h); }

// SMEM layout (bytes). W/x staging buffers reused across b-phase and a-phase.
#define OFF_KS   0          // float[32][512]      65536
#define OFF_US   65536      // float[64]             256
#define OFF_AQ   65792      // u32[32][8]           1024  (int8-packed a rows)
#define OFF_WT   66816      // u32[32][132]        16896  (half2 W, transposed, padded)
#define OFF_XS   83712      // u32[32][132]        16896  (half2 x rows, padded)
#define OFF_CP   100608     // float[2][512]        4096  (half column partials)
#define SMEM_BYTES 104704

__global__ void __launch_bounds__(STH, 1) sinkhorn_fused(
    float* __restrict__ out,
    const float* __restrict__ in_emb, const int* __restrict__ mask,
    const float* __restrict__ out_emb, const float* __restrict__ pad,
    const float* __restrict__ pos, const float* __restrict__ W_in,
    const float* __restrict__ b_in, const float* __restrict__ W_out,
    const float* __restrict__ b_out)
{
    extern __shared__ char smx[];
    float*    Ks  = (float*)(smx + OFF_KS);
    float*    uS  = (float*)(smx + OFF_US);
    unsigned* aQ  = (unsigned*)(smx + OFF_AQ);
    unsigned* Wt2 = (unsigned*)(smx + OFF_WT);
    unsigned* xS2 = (unsigned*)(smx + OFF_XS);
    float*    cpS = (float*)(smx + OFF_CP);
    __shared__ float red[32];

    int tid = threadIdx.x;
    int b   = blockIdx.x >> 4;
    int blk = blockIdx.x & 15;
    int i0  = blk * 32;
    int w   = tid >> 5, lane = tid & 31;
    int j   = tid & 511;           // column owned by this thread
    int h   = tid >> 9;            // row-half: rows h*16 .. h*16+15
    // Seed phase from persistent global: any gens-per-launch parity is replay-safe.
    int phase = (int)*(volatile unsigned*)&gBarPhase[b];

    // ============ PHASE B: stage W_in + b-x rows, b-GEMM (32 warps, 1 row each), publish int8 ============
    for (int k = tid; k < 32 * 128; k += STH) {
        int c = k & 31, du = k >> 5;
        Wt2[c * 132 + du] = h2u(__floats2half2_rn(W_in[(2 * du) * 32 + c],
                                                  W_in[(2 * du + 1) * 32 + c]));
    }
    for (int k = tid; k < 32 * 128; k += STH) {
        int du = k & 127, rl = k >> 7;
        int g = b * 512 + i0 + rl;
        float f0, f1;
        if (mask[g] != 0) { float2 e = *(const float2*)(pad + 2 * du); f0 = e.x; f1 = e.y; }
        else { float2 e = *(const float2*)(in_emb + (size_t)g * 256 + 2 * du); f0 = e.x; f1 = e.y; }
        xS2[rl * 132 + du] = h2u(__floats2half2_rn(f0, f1));
    }
    __syncthreads();

    // GEMM macro: warp w computes output row w (32 cols = lanes); result quantized to int8
    // scale QS, packed 4 lanes/word by lanes with (lane&3)==0.
#define GEMM1(BIAS, STORE)                                                         \
    {                                                                              \
        const uint4* wrow = (const uint4*)(Wt2 + lane * 132);                      \
        const uint4* x0 = (const uint4*)(xS2 + w * 132);                           \
        half2 z = __floats2half2_rn(0.f, 0.f);                                     \
        half2 aa = z, ab = z;                                                      \
        _Pragma("unroll")                                                          \
        for (int q = 0; q < 16; q++) {                                             \
            uint4 wv = wrow[q]; uint4 v0 = x0[q];                                  \
            aa = __hfma2(u2h(v0.x), u2h(wv.x), aa); aa = __hfma2(u2h(v0.y), u2h(wv.y), aa); \
            aa = __hfma2(u2h(v0.z), u2h(wv.z), aa); aa = __hfma2(u2h(v0.w), u2h(wv.w), aa); \
        }                                                                          \
        _Pragma("unroll")                                                          \
        for (int q = 16; q < 32; q++) {                                            \
            uint4 wv = wrow[q]; uint4 v0 = x0[q];                                  \
            ab = __hfma2(u2h(v0.x), u2h(wv.x), ab); ab = __hfma2(u2h(v0.y), u2h(wv.y), ab); \
            ab = __hfma2(u2h(v0.z), u2h(wv.z), ab); ab = __hfma2(u2h(v0.w), u2h(wv.w), ab); \
        }                                                                          \
        float bias = (BIAS)[lane];                                                 \
        float2 fa = __half22float2(aa);                                            \
        float2 fb = __half22float2(ab);                                            \
        float res = bias + (fa.x + fa.y) + (fb.x + fb.y);                          \
        int qi = __float2int_rn(res * QS);                                         \
        qi = max(-127, min(127, qi));                                              \
        unsigned qb = (unsigned)qi & 0xffu;                                        \
        unsigned b1 = __shfl_down_sync(0xffffffffu, qb, 1);                        \
        unsigned b2 = __shfl_down_sync(0xffffffffu, qb, 2);                        \
        unsigned b3 = __shfl_down_sync(0xffffffffu, qb, 3);                        \
        if (!(lane & 3)) {                                                         \
            unsigned pk = qb | (b1 << 8) | (b2 << 16) | (b3 << 24);                \
            STORE;                                                                 \
        }                                                                          \
    }

    GEMM1(b_in, gBq[((size_t)b * 512 + i0 + w) * 8 + (lane >> 2)] = pk)

    bool last1 = bar_arrive(b, phase);        // gen 1 arrive: gBq published; overlap a-side below

    // ============ PHASE A (inside gen-1 wait window): stage W_out + a-x rows, a-GEMM ============
    for (int k = tid; k < 32 * 128; k += STH) {
        int c = k & 31, du = k >> 5;
        Wt2[c * 132 + du] = h2u(__floats2half2_rn(W_out[(2 * du) * 32 + c],
                                                  W_out[(2 * du + 1) * 32 + c]));
    }
    for (int k = tid; k < 32 * 128; k += STH) {
        int du = k & 127, rl = k >> 7;
        int g = b * 512 + i0 + rl;
        float2 e = *(const float2*)(out_emb + (size_t)g * 256 + 2 * du);
        float2 p = *(const float2*)(pos + (size_t)(i0 + rl) * 256 + 2 * du);
        xS2[rl * 132 + du] = h2u(__floats2half2_rn(e.x + p.x, e.y + p.y));
    }
    __syncthreads();

    GEMM1(b_out, aQ[w * 8 + (lane >> 2)] = pk)
#undef GEMM1

    bar_wait(b, phase, last1);                // gen 1 complete (ends with __syncthreads)

    // ---- bq regs: b-row j (32 B int8, 2x LDG.128 from L2; both halves read same row) ----
    uint4 bq0, bq1;
    {
        const uint4* brow = (const uint4*)(gBq + ((size_t)b * 512 + j) * 8);
        bq0 = __ldcg(brow + 0);
        bq1 = __ldcg(brow + 1);
    }

    // ---- int8 cost build (16 rows per thread): C_ij = sum_m |qa - qb| / QS ----
    float localsum = 0.f;
    int ibase = h << 4;
    for (int ii = 0; ii < 16; ii++) {
        int i = ibase + ii;
        const uint4* ar = (const uint4*)(aQ + i * 8);   // broadcast within half
        uint4 A0 = ar[0], A1 = ar[1];
        unsigned acc = 0;
        acc = __dp4a(__vabsdiffs4((int)A0.x, (int)bq0.x), 0x01010101u, acc);
        acc = __dp4a(__vabsdiffs4((int)A0.y, (int)bq0.y), 0x01010101u, acc);
        acc = __dp4a(__vabsdiffs4((int)A0.z, (int)bq0.z), 0x01010101u, acc);
        acc = __dp4a(__vabsdiffs4((int)A0.w, (int)bq0.w), 0x01010101u, acc);
        acc = __dp4a(__vabsdiffs4((int)A1.x, (int)bq1.x), 0x01010101u, acc);
        acc = __dp4a(__vabsdiffs4((int)A1.y, (int)bq1.y), 0x01010101u, acc);
        acc = __dp4a(__vabsdiffs4((int)A1.z, (int)bq1.z), 0x01010101u, acc);
        acc = __dp4a(__vabsdiffs4((int)A1.w, (int)bq1.w), 0x01010101u, acc);
        float cst = (float)acc * QSI;
        Ks[(i << 9) + j] = cst;
        localsum += cst;
    }

    // deterministic block sum -> gSpart[b][blk]
#pragma unroll
    for (int off = 16; off; off >>= 1)
        localsum += __shfl_xor_sync(0xffffffffu, localsum, off);
    if (lane == 0) red[w] = localsum;
    __syncthreads();
    if (tid == 0) {
        float s = 0.f;
#pragma unroll
        for (int k = 0; k < 32; k++) s += red[k];
        gSpart[b][blk] = s;
    }

    bool last2 = bar_arrive(b, phase);        // gen 2
    bar_wait(b, phase, last2);

    float Ssum = 0.f;
#pragma unroll
    for (int k = 0; k < 16; k++) Ssum += __ldcg(&gSpart[b][k]);
    float alpha = -1.0f / (EPSILON * Ssum);

    float kr[16];
#pragma unroll
    for (int ii = 0; ii < 16; ii++) {
        int i = ibase + ii;
        float kv = __expf(Ks[(i << 9) + j] * alpha);
        Ks[(i << 9) + j] = kv;
        kr[ii] = kv;
    }
    __syncthreads();

    // ---- u_i = MARG / rowsum_i (v0 = 1); 1 row per warp, 32 warps ----
    {
        float s = 0.f;
#pragma unroll
        for (int jj = 0; jj < 16; jj++)
            s += Ks[(w << 9) + (jj << 5) + lane];
#pragma unroll
        for (int off = 16; off; off >>= 1)
            s += __shfl_xor_sync(0xffffffffu, s, off);
        if (lane == 0) uS[w] = MARG / s;
    }
    __syncthreads();

    // ---- kr_i *= u_i ; half-column partial; combine halves deterministically ----
    float c = 0.f;
#pragma unroll
    for (int ii = 0; ii < 16; ii++) { kr[ii] *= uS[ibase + ii]; c += kr[ii]; }
    cpS[(h << 9) + j] = c;
    __syncthreads();
    if (h == 0)
        gPartial[b][blk][j] = cpS[j] + cpS[512 + j];

    bool last3 = bar_arrive(b, phase);        // gen 3
    bar_wait(b, phase, last3);

    // ---- epilogue: v_j then P_ij = kr_ii * v_j (16 rows per thread) ----
    {
        const float* pp = &gPartial[b][0][j];
        float cs = 0.f;
#pragma unroll
        for (int k = 0; k < NBLK; k++) cs += __ldcg(pp + (k << 9));
        float vj = MARG / cs;
        float* o = out + ((size_t)(b * 512 + i0 + ibase)) * 512 + j;
#pragma unroll
        for (int ii = 0; ii < 16; ii++)
            o[(size_t)ii * 512] = kr[ii] * vj;
    }
}

extern "C" void kernel_launch(void* const* d_in, const int* in_sizes, int n_in,
                              void* d_out, int out_size) {
    const float* in_emb  = (const float*)d_in[0];
    const int*   mask    = (const int*)d_in[1];
    const float* out_emb = (const float*)d_in[2];
    const float* pad     = (const float*)d_in[3];
    const float* pos     = (const float*)d_in[4];
    const float* W_in    = (const float*)d_in[5];
    const float* b_in    = (const float*)d_in[6];
    const float* W_out   = (const float*)d_in[7];
    const float* b_out   = (const float*)d_in[8];

    cudaFuncSetAttribute(sinkhorn_fused,
                         cudaFuncAttributeMaxDynamicSharedMemorySize,
                         SMEM_BYTES);

    sinkhorn_fused<<<NCTA, STH, SMEM_BYTES>>>((float*)d_out,
                                              in_emb, mask, out_emb, pad, pos,
                                              W_in, b_in, W_out, b_out);
}

// round 17
// speedup vs baseline: 1.1434x; 1.1434x over previous
#include <cuda_runtime.h>
#include <cuda_fp16.h>

#define EPSILON 1e-4f
#define MARG    0.001953125f    // 1/512
#define NBLK    16
#define NCTA    128
#define STH     512
#define QS      16.0f           // int8 quant scale (step 1/16); 1/QS cancels in C*alpha

// Scratch (static device globals — no allocation)
__device__ unsigned gBq[8 * 512 * 8];         // int8-packed b rows: [row][8 u32] = 32 bytes
__device__ float    gPartial[8][16][512];     // col partial sums
__device__ float    gSpart[8][16];            // per-block cost sums (raw int counts as float)
__device__ unsigned gBarCnt[8];               // barrier counters (self-reset per gen)
__device__ unsigned gBarPhase[8];             // phase flags; local phase seeded at entry

// ---- split-phase sense-reversing barrier: 16 arrivals per batch ----
__device__ __forceinline__ bool bar_arrive(int b, int phase) {
    __syncthreads();
    bool last = false;
    if (threadIdx.x == 0) {
        unsigned old;
        asm volatile("atom.acq_rel.gpu.global.add.u32 %0, [%1], %2;"
                     : "=r"(old) : "l"(&gBarCnt[b]), "r"(1u) : "memory");
        if (old == NBLK - 1) {
            unsigned z = 0, np = (unsigned)(phase ^ 1);
            asm volatile("st.relaxed.gpu.global.u32 [%0], %1;" :: "l"(&gBarCnt[b]), "r"(z) : "memory");
            asm volatile("st.release.gpu.global.u32 [%0], %1;" :: "l"(&gBarPhase[b]), "r"(np) : "memory");
            last = true;
        }
    }
    return last;   // meaningful on tid 0 only
}
__device__ __forceinline__ void bar_wait(int b, int& phase, bool last) {
    if (threadIdx.x == 0 && !last) {
        unsigned cur;
        do {
            asm volatile("ld.acquire.gpu.global.u32 %0, [%1];"
                         : "=r"(cur) : "l"(&gBarPhase[b]) : "memory");
        } while (cur == (unsigned)phase);
    }
    phase ^= 1;
    __syncthreads();
}

__device__ __forceinline__ half2 u2h(unsigned u) { return *reinterpret_cast<half2*>(&u); }
__device__ __forceinline__ unsigned h2u(half2 h) { return *reinterpret_cast<unsigned*>(&h); }

// SMEM layout (bytes). W/x staging buffers reused across b-phase and a-phase.
#define OFF_KS   0          // float[32][512]      65536
#define OFF_US   65536      // float[64]             256
#define OFF_AQ   65792      // u32[32][8]           1024  (int8-packed a rows)
#define OFF_WT   66816      // u32[32][132]        16896  (half2 W, transposed, padded)
#define OFF_XS   83712      // u32[32][132]        16896  (half2 x rows, padded)
#define SMEM_BYTES 100608

__global__ void __launch_bounds__(STH, 1) sinkhorn_fused(
    float* __restrict__ out,
    const float* __restrict__ in_emb, const int* __restrict__ mask,
    const float* __restrict__ out_emb, const float* __restrict__ pad,
    const float* __restrict__ pos, const float* __restrict__ W_in,
    const float* __restrict__ b_in, const float* __restrict__ W_out,
    const float* __restrict__ b_out)
{
    extern __shared__ char smx[];
    float*    Ks  = (float*)(smx + OFF_KS);
    float*    uS  = (float*)(smx + OFF_US);
    unsigned* aQ  = (unsigned*)(smx + OFF_AQ);
    unsigned* Wt2 = (unsigned*)(smx + OFF_WT);
    unsigned* xS2 = (unsigned*)(smx + OFF_XS);
    __shared__ unsigned redU[16];

    int tid = threadIdx.x;
    int b   = blockIdx.x >> 4;
    int blk = blockIdx.x & 15;
    int i0  = blk * 32;
    int w   = tid >> 5, lane = tid & 31;
    // Seed phase from persistent global: any gens-per-launch parity is replay-safe.
    int phase = (int)*(volatile unsigned*)&gBarPhase[b];

    // ============ PHASE B: stage W_in + b-x rows, b-GEMM (ALL 16 warps), publish int8 ============
    for (int k = tid; k < 32 * 128; k += STH) {
        int c = k & 31, du = k >> 5;
        Wt2[c * 132 + du] = h2u(__floats2half2_rn(W_in[(2 * du) * 32 + c],
                                                  W_in[(2 * du + 1) * 32 + c]));
    }
    for (int k = tid; k < 32 * 128; k += STH) {
        int du = k & 127, rl = k >> 7;
        int g = b * 512 + i0 + rl;
        float f0, f1;
        if (mask[g] != 0) { float2 e = *(const float2*)(pad + 2 * du); f0 = e.x; f1 = e.y; }
        else { float2 e = *(const float2*)(in_emb + (size_t)g * 256 + 2 * du); f0 = e.x; f1 = e.y; }
        xS2[rl * 132 + du] = h2u(__floats2half2_rn(f0, f1));
    }
    __syncthreads();

    // GEMM macro: computes rows 2w,2w+1; result res (fp32) quantized to int8 scale QS,
    // packed 4 lanes/word, stored by lanes with (lane&3)==0 at word index lane>>2.
#define GEMM2(BIAS, STORE)                                                         \
    {                                                                              \
        const uint4* wrow = (const uint4*)(Wt2 + lane * 132);                      \
        const uint4* x0 = (const uint4*)(xS2 + (2 * w + 0) * 132);                 \
        const uint4* x1 = (const uint4*)(xS2 + (2 * w + 1) * 132);                 \
        half2 z = __floats2half2_rn(0.f, 0.f);                                     \
        half2 a0a = z, a1a = z, a0b = z, a1b = z;                                  \
        _Pragma("unroll")                                                          \
        for (int q = 0; q < 16; q++) {                                             \
            uint4 wv = wrow[q]; uint4 v0 = x0[q], v1 = x1[q];                      \
            a0a = __hfma2(u2h(v0.x), u2h(wv.x), a0a); a0a = __hfma2(u2h(v0.y), u2h(wv.y), a0a); \
            a0a = __hfma2(u2h(v0.z), u2h(wv.z), a0a); a0a = __hfma2(u2h(v0.w), u2h(wv.w), a0a); \
            a1a = __hfma2(u2h(v1.x), u2h(wv.x), a1a); a1a = __hfma2(u2h(v1.y), u2h(wv.y), a1a); \
            a1a = __hfma2(u2h(v1.z), u2h(wv.z), a1a); a1a = __hfma2(u2h(v1.w), u2h(wv.w), a1a); \
        }                                                                          \
        _Pragma("unroll")                                                          \
        for (int q = 16; q < 32; q++) {                                            \
            uint4 wv = wrow[q]; uint4 v0 = x0[q], v1 = x1[q];                      \
            a0b = __hfma2(u2h(v0.x), u2h(wv.x), a0b); a0b = __hfma2(u2h(v0.y), u2h(wv.y), a0b); \
            a0b = __hfma2(u2h(v0.z), u2h(wv.z), a0b); a0b = __hfma2(u2h(v0.w), u2h(wv.w), a0b); \
            a1b = __hfma2(u2h(v1.x), u2h(wv.x), a1b); a1b = __hfma2(u2h(v1.y), u2h(wv.y), a1b); \
            a1b = __hfma2(u2h(v1.z), u2h(wv.z), a1b); a1b = __hfma2(u2h(v1.w), u2h(wv.w), a1b); \
        }                                                                          \
        float bias = (BIAS)[lane];                                                 \
        half2 accA[2] = {a0a, a1a};                                                \
        half2 accB[2] = {a0b, a1b};                                                \
        _Pragma("unroll")                                                          \
        for (int r = 0; r < 2; r++) {                                              \
            float2 fa = __half22float2(accA[r]);                                   \
            float2 fb = __half22float2(accB[r]);                                   \
            float res = bias + (fa.x + fa.y) + (fb.x + fb.y);                      \
            int qi = __float2int_rn(res * QS);                                     \
            qi = max(-127, min(127, qi));                                          \
            unsigned qb = (unsigned)qi & 0xffu;                                    \
            unsigned b1 = __shfl_down_sync(0xffffffffu, qb, 1);                    \
            unsigned b2 = __shfl_down_sync(0xffffffffu, qb, 2);                    \
            unsigned b3 = __shfl_down_sync(0xffffffffu, qb, 3);                    \
            if (!(lane & 3)) {                                                     \
                unsigned pk = qb | (b1 << 8) | (b2 << 16) | (b3 << 24);            \
                STORE;                                                             \
            }                                                                      \
        }                                                                          \
    }

    GEMM2(b_in, gBq[((size_t)b * 512 + i0 + 2 * w + r) * 8 + (lane >> 2)] = pk)

    bool last1 = bar_arrive(b, phase);        // gen 1 arrive: gBq published; overlap a-side below

    // ============ PHASE A (inside gen-1 wait window): stage W_out + a-x rows, a-GEMM ============
    for (int k = tid; k < 32 * 128; k += STH) {
        int c = k & 31, du = k >> 5;
        Wt2[c * 132 + du] = h2u(__floats2half2_rn(W_out[(2 * du) * 32 + c],
                                                  W_out[(2 * du + 1) * 32 + c]));
    }
    for (int k = tid; k < 32 * 128; k += STH) {
        int du = k & 127, rl = k >> 7;
        int g = b * 512 + i0 + rl;
        float2 e = *(const float2*)(out_emb + (size_t)g * 256 + 2 * du);
        float2 p = *(const float2*)(pos + (size_t)(i0 + rl) * 256 + 2 * du);
        xS2[rl * 132 + du] = h2u(__floats2half2_rn(e.x + p.x, e.y + p.y));
    }
    __syncthreads();

    GEMM2(b_out, aQ[(2 * w + r) * 8 + (lane >> 2)] = pk)
#undef GEMM2

    bar_wait(b, phase, last1);                // gen 1 complete (ends with __syncthreads)

    // ---- bq regs: this thread's b-row j = tid (32 B int8, 2x LDG.128 from L2) ----
    uint4 bq0, bq1;
    {
        const uint4* brow = (const uint4*)(gBq + ((size_t)b * 512 + tid) * 8);
        bq0 = __ldcg(brow + 0);
        bq1 = __ldcg(brow + 1);
    }

    // ---- int8 cost build: raw count C'_ij = sum_m |qa - qb|  (scale 1/QS cancels in alpha) ----
    unsigned localsum = 0u;
    for (int i = 0; i < 32; i++) {
        const uint4* ar = (const uint4*)(aQ + i * 8);   // broadcast
        uint4 A0 = ar[0], A1 = ar[1];
        unsigned acc = 0;
        acc = __dp4a(__vabsdiffs4((int)A0.x, (int)bq0.x), 0x01010101u, acc);
        acc = __dp4a(__vabsdiffs4((int)A0.y, (int)bq0.y), 0x01010101u, acc);
        acc = __dp4a(__vabsdiffs4((int)A0.z, (int)bq0.z), 0x01010101u, acc);
        acc = __dp4a(__vabsdiffs4((int)A0.w, (int)bq0.w), 0x01010101u, acc);
        acc = __dp4a(__vabsdiffs4((int)A1.x, (int)bq1.x), 0x01010101u, acc);
        acc = __dp4a(__vabsdiffs4((int)A1.y, (int)bq1.y), 0x01010101u, acc);
        acc = __dp4a(__vabsdiffs4((int)A1.z, (int)bq1.z), 0x01010101u, acc);
        acc = __dp4a(__vabsdiffs4((int)A1.w, (int)bq1.w), 0x01010101u, acc);
        Ks[(i << 9) + tid] = (float)acc;               // raw count as float
        localsum += acc;                               // exact integer accumulation
    }

    // deterministic (exact) integer block sum -> gSpart[b][blk]
#pragma unroll
    for (int off = 16; off; off >>= 1)
        localsum += __shfl_xor_sync(0xffffffffu, localsum, off);
    if (lane == 0) redU[w] = localsum;
    __syncthreads();
    if (tid == 0) {
        unsigned s = 0u;
#pragma unroll
        for (int k = 0; k < 16; k++) s += redU[k];
        gSpart[b][blk] = (float)s;
    }

    bool last2 = bar_arrive(b, phase);        // gen 2
    bar_wait(b, phase, last2);

    float Ssum = 0.f;
#pragma unroll
    for (int k = 0; k < 16; k++) Ssum += __ldcg(&gSpart[b][k]);
    float alpha = -1.0f / (EPSILON * Ssum);   // C*alpha = -acc/(eps*Sum(acc)): QS cancels exactly

    float kr[32];
#pragma unroll
    for (int i = 0; i < 32; i++) {
        float kv = __expf(Ks[(i << 9) + tid] * alpha);
        Ks[(i << 9) + tid] = kv;
        kr[i] = kv;
    }
    __syncthreads();

    // ---- u_i = MARG / rowsum_i (v0 = 1); 2 rows per warp ----
#pragma unroll
    for (int r = 0; r < 2; r++) {
        int i = (w << 1) + r;
        float s = 0.f;
#pragma unroll
        for (int jj = 0; jj < 16; jj++)
            s += Ks[(i << 9) + (jj << 5) + lane];
#pragma unroll
        for (int off = 16; off; off >>= 1)
            s += __shfl_xor_sync(0xffffffffu, s, off);
        if (lane == 0) uS[i] = MARG / s;
    }
    __syncthreads();

    // ---- pr_i = K_i,tid * u_i ; column partial c = sum_i pr_i ----
    float pr[32];
    float c = 0.f;
#pragma unroll
    for (int i = 0; i < 32; i++) { pr[i] = kr[i] * uS[i]; c += pr[i]; }
    gPartial[b][blk][tid] = c;

    bool last3 = bar_arrive(b, phase);        // gen 3
    bar_wait(b, phase, last3);

    // ---- epilogue: v_j then P_ij = pr_i * v_j ----
    {
        const float* pp = &gPartial[b][0][tid];
        float cs = 0.f;
#pragma unroll
        for (int k = 0; k < NBLK; k++) cs += __ldcg(pp + (k << 9));
        float vj = MARG / cs;
        float* o = out + ((size_t)(b * 512 + i0)) * 512 + tid;
#pragma unroll
        for (int i = 0; i < 32; i++)
            o[(size_t)i * 512] = pr[i] * vj;
    }
}

extern "C" void kernel_launch(void* const* d_in, const int* in_sizes, int n_in,
                              void* d_out, int out_size) {
    const float* in_emb  = (const float*)d_in[0];
    const int*   mask    = (const int*)d_in[1];
    const float* out_emb = (const float*)d_in[2];
    const float* pad     = (const float*)d_in[3];
    const float* pos     = (const float*)d_in[4];
    const float* W_in    = (const float*)d_in[5];
    const float* b_in    = (const float*)d_in[6];
    const float* W_out   = (const float*)d_in[7];
    const float* b_out   = (const float*)d_in[8];

    cudaFuncSetAttribute(sinkhorn_fused,
                         cudaFuncAttributeMaxDynamicSharedMemorySize,
                         SMEM_BYTES);

    sinkhorn_fused<<<NCTA, STH, SMEM_BYTES>>>((float*)d_out,
                                              in_emb, mask, out_emb, pad, pos,
                                              W_in, b_in, W_out, b_out);
}